// round 1
// baseline (speedup 1.0000x reference)
#include <cuda_runtime.h>
#include <math.h>

#define BB 8
#define SEQL 256
#define MEML 768
#define TOT 1024
#define DIMM 512
#define NH 8
#define DH 64
#define INNERD 512
#define CTXL 1024
#define NOCTL 11
#define SSTR 1028   // S row stride in floats (1024 + 4 to break bank alignment)

// ---------------- scratch (device globals; no allocation allowed) ----------------
__device__ float g_QU[BB*NH*SEQL*DH];           // q + u_emb   (4 MB)
__device__ float g_QV[BB*NH*SEQL*DH];           // q + v_emb   (4 MB)
__device__ float g_K [(size_t)BB*NH*TOT*DH];    // 16 MB
__device__ float g_V [(size_t)BB*NH*TOT*DH];    // 16 MB
__device__ float g_Krel[NH*CTXL*DH];            // (R @ W_rel) as [h][s][d]  (2 MB)
__device__ float g_BD[(size_t)BB*NH*SEQL*CTXL]; // qv . Krel^T  (64 MB)
__device__ float g_AO[BB*SEQL*INNERD];          // attention output, [b][n][h*64+d] (4 MB)

// =====================================================================
// Kernel 1: QKV projection.  C[8192 x 1536] = concat(memory,x)[8192 x 512] @ W_qkv
// 64x64 tile, BK=32, 256 threads, 4x4 register micro-tile.
// Scatters into K, V, QU(+u), QV(+v) head-major layouts.
// =====================================================================
__global__ __launch_bounds__(256) void qkv_kernel(
    const float* __restrict__ x, const float* __restrict__ mm,
    const float* __restrict__ W, const float* __restrict__ u_emb,
    const float* __restrict__ v_emb)
{
    __shared__ float AsT[32][68];  // [k][row]
    __shared__ float Bs [32][68];  // [k][col]
    int t  = threadIdx.x;
    int tx = t & 15, ty = t >> 4;
    int r0 = blockIdx.y * 64;
    int c0 = blockIdx.x * 64;

    float acc[4][4];
#pragma unroll
    for (int i = 0; i < 4; i++)
#pragma unroll
        for (int j = 0; j < 4; j++) acc[i][j] = 0.f;

    for (int k0 = 0; k0 < DIMM; k0 += 32) {
        {   // A tile: 64 rows x 32 k  (float4 along k), store transposed
            int k4  = t & 7;
            int row = t >> 3;   // 0..31
#pragma unroll
            for (int rr = row; rr < 64; rr += 32) {
                int gr = r0 + rr;
                int b = gr >> 10, pos = gr & 1023;
                const float* src = (pos < MEML)
                    ? (mm + ((size_t)(b*MEML + pos))*DIMM)
                    : (x  + ((size_t)(b*SEQL + pos - MEML))*DIMM);
                float4 v = *(const float4*)(src + k0 + k4*4);
                AsT[k4*4+0][rr] = v.x; AsT[k4*4+1][rr] = v.y;
                AsT[k4*4+2][rr] = v.z; AsT[k4*4+3][rr] = v.w;
            }
        }
        {   // B tile: 32 k x 64 cols (float4 along cols)
            int c4 = t & 15;
            int kr = t >> 4;    // 0..15
#pragma unroll
            for (int kk = kr; kk < 32; kk += 16) {
                float4 w = *(const float4*)(W + (size_t)(k0+kk)*1536 + c0 + c4*4);
                *(float4*)&Bs[kk][c4*4] = w;
            }
        }
        __syncthreads();
#pragma unroll
        for (int kk = 0; kk < 32; kk++) {
            float4 a4 = *(float4*)&AsT[kk][ty*4];
            float4 b4 = *(float4*)&Bs [kk][tx*4];
            acc[0][0] += a4.x*b4.x; acc[0][1] += a4.x*b4.y; acc[0][2] += a4.x*b4.z; acc[0][3] += a4.x*b4.w;
            acc[1][0] += a4.y*b4.x; acc[1][1] += a4.y*b4.y; acc[1][2] += a4.y*b4.z; acc[1][3] += a4.y*b4.w;
            acc[2][0] += a4.z*b4.x; acc[2][1] += a4.z*b4.y; acc[2][2] += a4.z*b4.z; acc[2][3] += a4.z*b4.w;
            acc[3][0] += a4.w*b4.x; acc[3][1] += a4.w*b4.y; acc[3][2] += a4.w*b4.z; acc[3][3] += a4.w*b4.w;
        }
        __syncthreads();
    }

#pragma unroll
    for (int i = 0; i < 4; i++) {
        int gr = r0 + ty*4 + i;
        int b = gr >> 10, pos = gr & 1023;
#pragma unroll
        for (int j = 0; j < 4; j++) {
            int c = c0 + tx*4 + j;
            int which = c >> 9;       // 0=q, 1=k, 2=v
            int cc = c & 511;
            int h = cc >> 6, d = cc & 63;
            float val = acc[i][j];
            if (which == 1) {
                g_K[(((size_t)(b*NH + h))*TOT + pos)*DH + d] = val;
            } else if (which == 2) {
                g_V[(((size_t)(b*NH + h))*TOT + pos)*DH + d] = val;
            } else if (pos >= MEML) {
                int n = pos - MEML;
                size_t idx = (((size_t)(b*NH + h))*SEQL + n)*DH + d;
                g_QU[idx] = val + u_emb[d];
                g_QV[idx] = val + v_emb[d];
            }
        }
    }
}

// =====================================================================
// Kernel 2: Krel[s, h, d] = (posenc(s) @ W_rel), stored [h][s][d]
// =====================================================================
__global__ __launch_bounds__(512) void krel_kernel(const float* __restrict__ Wrel)
{
    __shared__ float R[2*NOCTL];
    int s = blockIdx.x;
    int t = threadIdx.x;
    if (t < NOCTL) {
        float mult = exp2f((float)(t - (NOCTL-1))) * 3.14159265358979323846f;
        float arg = (float)s * mult;
        R[t]         = sinf(arg);
        R[t + NOCTL] = cosf(arg);
    }
    __syncthreads();
    float acc = 0.f;
#pragma unroll
    for (int j = 0; j < 2*NOCTL; j++) acc += R[j] * Wrel[j*INNERD + t];
    int h = t >> 6, d = t & 63;
    g_Krel[((size_t)h*CTXL + s)*DH + d] = acc;
}

// =====================================================================
// Kernel 3: BD[b,h,n,s] = QV[b,h,n,:] . Krel[h,s,:]   (NT GEMM, K=64)
// grid (16 s-tiles, 4 n-tiles, 64 bh); 64x64 tile; 4x4 micro
// =====================================================================
__global__ __launch_bounds__(256) void bd_kernel()
{
    __shared__ float AsT[64][68];  // [d][n]
    __shared__ float BsT[64][68];  // [d][s]
    int t  = threadIdx.x;
    int tx = t & 15, ty = t >> 4;
    int bh = blockIdx.z;
    int h  = bh & 7;
    int n0 = blockIdx.y * 64;
    int s0 = blockIdx.x * 64;

    {
        int d4 = t & 15, row = t >> 4;
        const float* A  = g_QV   + ((size_t)bh*SEQL + n0)*DH;
        const float* Bk = g_Krel + ((size_t)h*CTXL + s0)*DH;
#pragma unroll
        for (int rr = row; rr < 64; rr += 16) {
            float4 a = *(const float4*)(A  + (size_t)rr*DH + d4*4);
            AsT[d4*4+0][rr] = a.x; AsT[d4*4+1][rr] = a.y;
            AsT[d4*4+2][rr] = a.z; AsT[d4*4+3][rr] = a.w;
            float4 b = *(const float4*)(Bk + (size_t)rr*DH + d4*4);
            BsT[d4*4+0][rr] = b.x; BsT[d4*4+1][rr] = b.y;
            BsT[d4*4+2][rr] = b.z; BsT[d4*4+3][rr] = b.w;
        }
    }
    __syncthreads();

    float acc[4][4];
#pragma unroll
    for (int i = 0; i < 4; i++)
#pragma unroll
        for (int j = 0; j < 4; j++) acc[i][j] = 0.f;

#pragma unroll
    for (int d = 0; d < 64; d++) {
        float4 a4 = *(float4*)&AsT[d][ty*4];
        float4 b4 = *(float4*)&BsT[d][tx*4];
        acc[0][0] += a4.x*b4.x; acc[0][1] += a4.x*b4.y; acc[0][2] += a4.x*b4.z; acc[0][3] += a4.x*b4.w;
        acc[1][0] += a4.y*b4.x; acc[1][1] += a4.y*b4.y; acc[1][2] += a4.y*b4.z; acc[1][3] += a4.y*b4.w;
        acc[2][0] += a4.z*b4.x; acc[2][1] += a4.z*b4.y; acc[2][2] += a4.z*b4.z; acc[2][3] += a4.z*b4.w;
        acc[3][0] += a4.w*b4.x; acc[3][1] += a4.w*b4.y; acc[3][2] += a4.w*b4.z; acc[3][3] += a4.w*b4.w;
    }

    float* out = g_BD + ((size_t)bh*SEQL + n0)*CTXL + s0;
#pragma unroll
    for (int i = 0; i < 4; i++)
#pragma unroll
        for (int j = 0; j < 4; j++)
            out[(size_t)(ty*4+i)*CTXL + tx*4 + j] = acc[i][j];
}

// =====================================================================
// Kernel 4: fused attention per (b,h, 32-query tile):
//   S = scale*(QU.K^T + BD[shifted])  with causal mask -> softmax -> P.V
// Dynamic smem: S[32][1028] + QUsT[64][36] + KV[64][68] + rinv[32]
// =====================================================================
#define ATTN_SMEM_FLOATS (32*SSTR + 64*36 + 64*68 + 32)

__global__ __launch_bounds__(256) void attn_kernel()
{
    extern __shared__ float smem[];
    float* S    = smem;                 // 32*SSTR
    float* QUsT = S + 32*SSTR;          // [d][n] stride 36
    float* KV   = QUsT + 64*36;         // [row][68]  (K transposed / V natural)
    float* rinv = KV + 64*68;           // 32

    int t  = threadIdx.x;
    int tx = t & 15, ty = t >> 4;
    int bh = blockIdx.y;
    int b  = bh >> 3, h = bh & 7;
    int n0 = blockIdx.x * 32;
    const float NEG_INF = __int_as_float(0xff800000);

    {   // load QU tile (32 x 64), transposed
        int d4 = t & 15, row = t >> 4;
        const float* Q = g_QU + ((size_t)bh*SEQL + n0)*DH;
#pragma unroll
        for (int rr = row; rr < 32; rr += 16) {
            float4 a = *(const float4*)(Q + (size_t)rr*DH + d4*4);
            QUsT[(d4*4+0)*36 + rr] = a.x; QUsT[(d4*4+1)*36 + rr] = a.y;
            QUsT[(d4*4+2)*36 + rr] = a.z; QUsT[(d4*4+3)*36 + rr] = a.w;
        }
    }

    // ---- phase 1: S = scale*(QU.K^T + BD_shifted), causal mask ----
    for (int m0 = 0; m0 < TOT; m0 += 64) {
        __syncthreads();
        {   // load K chunk (64 x 64), transposed into KV as [d][m]
            int d4 = t & 15, row = t >> 4;
            const float* Kp = g_K + ((size_t)bh*TOT + m0)*DH;
#pragma unroll
            for (int rr = row; rr < 64; rr += 16) {
                float4 a = *(const float4*)(Kp + (size_t)rr*DH + d4*4);
                KV[(d4*4+0)*68 + rr] = a.x; KV[(d4*4+1)*68 + rr] = a.y;
                KV[(d4*4+2)*68 + rr] = a.z; KV[(d4*4+3)*68 + rr] = a.w;
            }
        }
        __syncthreads();

        float acc[2][4] = {{0.f,0.f,0.f,0.f},{0.f,0.f,0.f,0.f}};
#pragma unroll 16
        for (int d = 0; d < 64; d++) {
            float a0 = QUsT[d*36 + ty*2];
            float a1 = QUsT[d*36 + ty*2 + 1];
            float4 b4 = *(float4*)&KV[d*68 + tx*4];
            acc[0][0] += a0*b4.x; acc[0][1] += a0*b4.y; acc[0][2] += a0*b4.z; acc[0][3] += a0*b4.w;
            acc[1][0] += a1*b4.x; acc[1][1] += a1*b4.y; acc[1][2] += a1*b4.z; acc[1][3] += a1*b4.w;
        }
#pragma unroll
        for (int i = 0; i < 2; i++) {
            int n  = ty*2 + i;
            int ng = n0 + n;
            const float* bdr = g_BD + ((size_t)bh*SEQL + ng)*CTXL;
            int limit = MEML + ng;     // valid m <= limit
            float vals[4];
#pragma unroll
            for (int j = 0; j < 4; j++) {
                int m = m0 + tx*4 + j;
                vals[j] = (m <= limit)
                    ? (acc[i][j] + bdr[limit - m]) * 0.125f
                    : NEG_INF;
            }
            *(float4*)&S[n*SSTR + m0 + tx*4] = make_float4(vals[0], vals[1], vals[2], vals[3]);
        }
    }
    __syncthreads();

    // ---- phase 2: softmax (unnormalized exp in S, 1/sum in rinv) ----
    {
        int warp = t >> 5, lane = t & 31;
        for (int q = 0; q < 4; q++) {
            int n = warp*4 + q;
            float* row = S + n*SSTR;
            float mx = NEG_INF;
            for (int m = lane; m < TOT; m += 32) mx = fmaxf(mx, row[m]);
#pragma unroll
            for (int o = 16; o; o >>= 1) mx = fmaxf(mx, __shfl_xor_sync(0xffffffffu, mx, o));
            float sum = 0.f;
            for (int m = lane; m < TOT; m += 32) {
                float e = __expf(row[m] - mx);
                row[m] = e;
                sum += e;
            }
#pragma unroll
            for (int o = 16; o; o >>= 1) sum += __shfl_xor_sync(0xffffffffu, sum, o);
            if (lane == 0) rinv[n] = 1.f / sum;
        }
    }
    __syncthreads();

    // ---- phase 3: O = P.V ----
    float oacc[2][4] = {{0.f,0.f,0.f,0.f},{0.f,0.f,0.f,0.f}};
    for (int m0 = 0; m0 < TOT; m0 += 64) {
        __syncthreads();
        {   // load V chunk natural [m][d]
            int d4 = t & 15, row = t >> 4;
            const float* Vp = g_V + ((size_t)bh*TOT + m0)*DH;
#pragma unroll
            for (int rr = row; rr < 64; rr += 16)
                *(float4*)&KV[rr*68 + d4*4] = *(const float4*)(Vp + (size_t)rr*DH + d4*4);
        }
        __syncthreads();
#pragma unroll 8
        for (int mm = 0; mm < 64; mm++) {
            float p0 = S[(ty*2  )*SSTR + m0 + mm];
            float p1 = S[(ty*2+1)*SSTR + m0 + mm];
            float4 v4 = *(float4*)&KV[mm*68 + tx*4];
            oacc[0][0] += p0*v4.x; oacc[0][1] += p0*v4.y; oacc[0][2] += p0*v4.z; oacc[0][3] += p0*v4.w;
            oacc[1][0] += p1*v4.x; oacc[1][1] += p1*v4.y; oacc[1][2] += p1*v4.z; oacc[1][3] += p1*v4.w;
        }
    }

#pragma unroll
    for (int i = 0; i < 2; i++) {
        int n  = ty*2 + i;
        int ng = n0 + n;
        float r = rinv[n];
        float4 o = make_float4(oacc[i][0]*r, oacc[i][1]*r, oacc[i][2]*r, oacc[i][3]*r);
        *(float4*)&g_AO[((size_t)(b*SEQL + ng))*INNERD + h*DH + tx*4] = o;
    }
}

// =====================================================================
// Kernel 5: out = AO[2048 x 512] @ W_out[512 x 512] + b_out
// =====================================================================
__global__ __launch_bounds__(256) void out_kernel(
    const float* __restrict__ W, const float* __restrict__ bias,
    float* __restrict__ out)
{
    __shared__ float AsT[32][68];
    __shared__ float Bs [32][68];
    int t  = threadIdx.x;
    int tx = t & 15, ty = t >> 4;
    int r0 = blockIdx.y * 64;
    int c0 = blockIdx.x * 64;

    float acc[4][4];
#pragma unroll
    for (int i = 0; i < 4; i++)
#pragma unroll
        for (int j = 0; j < 4; j++) acc[i][j] = 0.f;

    for (int k0 = 0; k0 < INNERD; k0 += 32) {
        {
            int k4  = t & 7;
            int row = t >> 3;
#pragma unroll
            for (int rr = row; rr < 64; rr += 32) {
                int gr = r0 + rr;
                float4 v = *(const float4*)(g_AO + (size_t)gr*INNERD + k0 + k4*4);
                AsT[k4*4+0][rr] = v.x; AsT[k4*4+1][rr] = v.y;
                AsT[k4*4+2][rr] = v.z; AsT[k4*4+3][rr] = v.w;
            }
        }
        {
            int c4 = t & 15;
            int kr = t >> 4;
#pragma unroll
            for (int kk = kr; kk < 32; kk += 16) {
                float4 w = *(const float4*)(W + (size_t)(k0+kk)*DIMM + c0 + c4*4);
                *(float4*)&Bs[kk][c4*4] = w;
            }
        }
        __syncthreads();
#pragma unroll
        for (int kk = 0; kk < 32; kk++) {
            float4 a4 = *(float4*)&AsT[kk][ty*4];
            float4 b4 = *(float4*)&Bs [kk][tx*4];
            acc[0][0] += a4.x*b4.x; acc[0][1] += a4.x*b4.y; acc[0][2] += a4.x*b4.z; acc[0][3] += a4.x*b4.w;
            acc[1][0] += a4.y*b4.x; acc[1][1] += a4.y*b4.y; acc[1][2] += a4.y*b4.z; acc[1][3] += a4.y*b4.w;
            acc[2][0] += a4.z*b4.x; acc[2][1] += a4.z*b4.y; acc[2][2] += a4.z*b4.z; acc[2][3] += a4.z*b4.w;
            acc[3][0] += a4.w*b4.x; acc[3][1] += a4.w*b4.y; acc[3][2] += a4.w*b4.z; acc[3][3] += a4.w*b4.w;
        }
        __syncthreads();
    }

#pragma unroll
    for (int i = 0; i < 4; i++) {
        int gr = r0 + ty*4 + i;
#pragma unroll
        for (int j = 0; j < 4; j++) {
            int c = c0 + tx*4 + j;
            out[(size_t)gr*DIMM + c] = acc[i][j] + bias[c];
        }
    }
}

// =====================================================================
extern "C" void kernel_launch(void* const* d_in, const int* in_sizes, int n_in,
                              void* d_out, int out_size)
{
    const float* x      = (const float*)d_in[0];
    const float* memory = (const float*)d_in[1];
    const float* Wqkv   = (const float*)d_in[2];
    const float* Wrel   = (const float*)d_in[3];
    const float* Wout   = (const float*)d_in[4];
    const float* bout   = (const float*)d_in[5];
    const float* u_emb  = (const float*)d_in[6];
    const float* v_emb  = (const float*)d_in[7];
    float* out = (float*)d_out;

    (void)in_sizes; (void)n_in; (void)out_size;

    cudaFuncSetAttribute(attn_kernel, cudaFuncAttributeMaxDynamicSharedMemorySize,
                         ATTN_SMEM_FLOATS * (int)sizeof(float));

    // 1. QKV projection (8192 x 512) @ (512 x 1536)
    qkv_kernel<<<dim3(1536/64, 8192/64), 256>>>(x, memory, Wqkv, u_emb, v_emb);
    // 2. Krel = posenc @ W_rel
    krel_kernel<<<CTXL, 512>>>(Wrel);
    // 3. BD = QV . Krel^T (per b,h)
    bd_kernel<<<dim3(CTXL/64, SEQL/64, BB*NH), 256>>>();
    // 4. fused attention
    attn_kernel<<<dim3(SEQL/32, BB*NH), 256, ATTN_SMEM_FLOATS * (int)sizeof(float)>>>();
    // 5. output projection + bias
    out_kernel<<<dim3(DIMM/64, 2048/64), 256>>>(Wout, bout, out);
}

// round 2
// speedup vs baseline: 1.1978x; 1.1978x over previous
#include <cuda_runtime.h>
#include <math.h>

#define BB 8
#define SEQL 256
#define MEML 768
#define TOT 1024
#define DIMM 512
#define NH 8
#define DH 64
#define INNERD 512
#define CTXL 1024
#define NOCTL 11

// ---------------- scratch (device globals; no allocation allowed) ----------------
__device__ float g_QU[BB*NH*SEQL*DH];           // q + u_emb   (4 MB)
__device__ float g_QV[BB*NH*SEQL*DH];           // q + v_emb   (4 MB)
__device__ float g_K [(size_t)BB*NH*TOT*DH];    // 16 MB
__device__ float g_V [(size_t)BB*NH*TOT*DH];    // 16 MB
__device__ float g_Krel[NH*CTXL*DH];            // (R @ W_rel) as [h][s][d]  (2 MB)
__device__ float g_BD[(size_t)BB*NH*SEQL*CTXL]; // qv . Krel^T  (64 MB)
__device__ float g_AO[BB*SEQL*INNERD];          // attention output, [b][n][h*64+d] (4 MB)

// =====================================================================
// Kernel 1: QKV projection.  C[8192 x 1536] = concat(memory,x)[8192 x 512] @ W_qkv
// 128x128 tile, BK=16, 256 threads, 8x8 register micro-tile.
// =====================================================================
__global__ __launch_bounds__(256) void qkv_kernel(
    const float* __restrict__ x, const float* __restrict__ mm,
    const float* __restrict__ W, const float* __restrict__ u_emb,
    const float* __restrict__ v_emb)
{
    __shared__ float AsT[16][132];  // [k][row]
    __shared__ float Bs [16][132];  // [k][col]
    int t  = threadIdx.x;
    int tx = t & 15, ty = t >> 4;
    int r0 = blockIdx.y * 128;
    int c0 = blockIdx.x * 128;

    float acc[8][8];
#pragma unroll
    for (int i = 0; i < 8; i++)
#pragma unroll
        for (int j = 0; j < 8; j++) acc[i][j] = 0.f;

    for (int k0 = 0; k0 < DIMM; k0 += 16) {
        __syncthreads();
        // A tile: 128 rows x 16 k. 512 float4, 2 per thread.
#pragma unroll
        for (int q = 0; q < 2; q++) {
            int fid = t*2 + q;
            int rr = fid >> 2, k4 = fid & 3;
            int gr = r0 + rr;
            int b = gr >> 10, pos = gr & 1023;
            const float* src = (pos < MEML)
                ? (mm + ((size_t)(b*MEML + pos))*DIMM)
                : (x  + ((size_t)(b*SEQL + pos - MEML))*DIMM);
            float4 v = *(const float4*)(src + k0 + k4*4);
            AsT[k4*4+0][rr] = v.x; AsT[k4*4+1][rr] = v.y;
            AsT[k4*4+2][rr] = v.z; AsT[k4*4+3][rr] = v.w;
        }
        // B tile: 16 k x 128 cols. 512 float4, 2 per thread.
#pragma unroll
        for (int q = 0; q < 2; q++) {
            int fid = t*2 + q;
            int kk = fid >> 5, c4 = fid & 31;
            *(float4*)&Bs[kk][c4*4] =
                *(const float4*)(W + (size_t)(k0+kk)*1536 + c0 + c4*4);
        }
        __syncthreads();
#pragma unroll
        for (int kk = 0; kk < 16; kk++) {
            float ar[8], br[8];
            float4 a0 = *(float4*)&AsT[kk][ty*8];
            float4 a1 = *(float4*)&AsT[kk][ty*8+4];
            float4 b0 = *(float4*)&Bs [kk][tx*8];
            float4 b1 = *(float4*)&Bs [kk][tx*8+4];
            ar[0]=a0.x; ar[1]=a0.y; ar[2]=a0.z; ar[3]=a0.w;
            ar[4]=a1.x; ar[5]=a1.y; ar[6]=a1.z; ar[7]=a1.w;
            br[0]=b0.x; br[1]=b0.y; br[2]=b0.z; br[3]=b0.w;
            br[4]=b1.x; br[5]=b1.y; br[6]=b1.z; br[7]=b1.w;
#pragma unroll
            for (int i = 0; i < 8; i++)
#pragma unroll
                for (int j = 0; j < 8; j++) acc[i][j] += ar[i]*br[j];
        }
    }

#pragma unroll
    for (int i = 0; i < 8; i++) {
        int gr = r0 + ty*8 + i;
        int b = gr >> 10, pos = gr & 1023;
#pragma unroll
        for (int j = 0; j < 8; j++) {
            int c = c0 + tx*8 + j;
            int which = c >> 9;       // 0=q, 1=k, 2=v
            int cc = c & 511;
            int h = cc >> 6, d = cc & 63;
            float val = acc[i][j];
            if (which == 1) {
                g_K[(((size_t)(b*NH + h))*TOT + pos)*DH + d] = val;
            } else if (which == 2) {
                g_V[(((size_t)(b*NH + h))*TOT + pos)*DH + d] = val;
            } else if (pos >= MEML) {
                int n = pos - MEML;
                size_t idx = (((size_t)(b*NH + h))*SEQL + n)*DH + d;
                g_QU[idx] = val + u_emb[d];
                g_QV[idx] = val + v_emb[d];
            }
        }
    }
}

// =====================================================================
// Kernel 2: Krel[s, h, d] = (posenc(s) @ W_rel), stored [h][s][d]
// =====================================================================
__global__ __launch_bounds__(512) void krel_kernel(const float* __restrict__ Wrel)
{
    __shared__ float R[2*NOCTL];
    int s = blockIdx.x;
    int t = threadIdx.x;
    if (t < NOCTL) {
        float mult = exp2f((float)(t - (NOCTL-1))) * 3.14159265358979323846f;
        float arg = (float)s * mult;
        R[t]         = sinf(arg);
        R[t + NOCTL] = cosf(arg);
    }
    __syncthreads();
    float acc = 0.f;
#pragma unroll
    for (int j = 0; j < 2*NOCTL; j++) acc += R[j] * Wrel[j*INNERD + t];
    int h = t >> 6, d = t & 63;
    g_Krel[((size_t)h*CTXL + s)*DH + d] = acc;
}

// =====================================================================
// Kernel 3: BD[b,h,n,s] = QV[b,h,n,:] . Krel[h,s,:]   (NT GEMM, K=64)
// =====================================================================
__global__ __launch_bounds__(256) void bd_kernel()
{
    __shared__ float AsT[64][68];  // [d][n]
    __shared__ float BsT[64][68];  // [d][s]
    int t  = threadIdx.x;
    int tx = t & 15, ty = t >> 4;
    int bh = blockIdx.z;
    int h  = bh & 7;
    int n0 = blockIdx.y * 64;
    int s0 = blockIdx.x * 64;

    // skip tiles never read by the shifted access (s <= MEML + n <= MEML+n0+63)
    if (s0 > MEML + n0 + 63) return;

    {
        int d4 = t & 15, row = t >> 4;
        const float* A  = g_QV   + ((size_t)bh*SEQL + n0)*DH;
        const float* Bk = g_Krel + ((size_t)h*CTXL + s0)*DH;
#pragma unroll
        for (int rr = row; rr < 64; rr += 16) {
            float4 a = *(const float4*)(A  + (size_t)rr*DH + d4*4);
            AsT[d4*4+0][rr] = a.x; AsT[d4*4+1][rr] = a.y;
            AsT[d4*4+2][rr] = a.z; AsT[d4*4+3][rr] = a.w;
            float4 b = *(const float4*)(Bk + (size_t)rr*DH + d4*4);
            BsT[d4*4+0][rr] = b.x; BsT[d4*4+1][rr] = b.y;
            BsT[d4*4+2][rr] = b.z; BsT[d4*4+3][rr] = b.w;
        }
    }
    __syncthreads();

    float acc[4][4];
#pragma unroll
    for (int i = 0; i < 4; i++)
#pragma unroll
        for (int j = 0; j < 4; j++) acc[i][j] = 0.f;

#pragma unroll
    for (int d = 0; d < 64; d++) {
        float4 a4 = *(float4*)&AsT[d][ty*4];
        float4 b4 = *(float4*)&BsT[d][tx*4];
        acc[0][0] += a4.x*b4.x; acc[0][1] += a4.x*b4.y; acc[0][2] += a4.x*b4.z; acc[0][3] += a4.x*b4.w;
        acc[1][0] += a4.y*b4.x; acc[1][1] += a4.y*b4.y; acc[1][2] += a4.y*b4.z; acc[1][3] += a4.y*b4.w;
        acc[2][0] += a4.z*b4.x; acc[2][1] += a4.z*b4.y; acc[2][2] += a4.z*b4.z; acc[2][3] += a4.z*b4.w;
        acc[3][0] += a4.w*b4.x; acc[3][1] += a4.w*b4.y; acc[3][2] += a4.w*b4.z; acc[3][3] += a4.w*b4.w;
    }

    float* out = g_BD + ((size_t)bh*SEQL + n0)*CTXL + s0;
#pragma unroll
    for (int i = 0; i < 4; i++)
#pragma unroll
        for (int j = 0; j < 4; j++)
            out[(size_t)(ty*4+i)*CTXL + tx*4 + j] = acc[i][j];
}

// =====================================================================
// Kernel 4: flash-style fused attention per (b,h, 64-query tile).
// Online softmax over 64-key tiles; skips fully-masked tiles.
// smem: QT/KT/VT/PT each 64x68 floats -> 68KB -> 3 CTAs/SM.
// =====================================================================
#define ATTN_SMEM_FLOATS (4*64*68)

__global__ __launch_bounds__(256) void attn_kernel()
{
    extern __shared__ float smem[];
    float* QT = smem;            // [d][n] stride 68
    float* KT = QT + 64*68;      // [d][m]
    float* VT = KT + 64*68;      // [m][d]
    float* PT = VT + 64*68;      // [n][m]

    int t  = threadIdx.x;
    int tx = t & 15, ty = t >> 4;
    int bh = blockIdx.y;
    int b  = bh >> 3, h = bh & 7;
    int n0 = blockIdx.x * 64;

    {   // load QU tile (64 x 64), transposed
        int d4 = t & 15, row = t >> 4;
        const float* Q = g_QU + ((size_t)bh*SEQL + n0)*DH;
#pragma unroll
        for (int rr = row; rr < 64; rr += 16) {
            float4 a = *(const float4*)(Q + (size_t)rr*DH + d4*4);
            QT[(d4*4+0)*68 + rr] = a.x; QT[(d4*4+1)*68 + rr] = a.y;
            QT[(d4*4+2)*68 + rr] = a.z; QT[(d4*4+3)*68 + rr] = a.w;
        }
    }

    float O[4][4];
    float M[4], L[4];
    const float* bdp[4];   // g_BD row base + limit  (access bdp[i][-m])
    int limit[4];
#pragma unroll
    for (int i = 0; i < 4; i++) {
        M[i] = -1e30f; L[i] = 0.f;
        int ng = n0 + ty*4 + i;
        limit[i] = MEML + ng;
        bdp[i] = g_BD + ((size_t)bh*SEQL + ng)*CTXL + limit[i];
#pragma unroll
        for (int j = 0; j < 4; j++) O[i][j] = 0.f;
    }

    int ntiles = (MEML + n0 + 63)/64 + 1;   // tiles with at least one unmasked key

    for (int tile = 0; tile < ntiles; tile++) {
        int m0 = tile * 64;
        __syncthreads();     // protect KT/VT/PT reuse from previous iteration
        {   // load K (transposed) and V (natural) chunks
            int d4 = t & 15, row = t >> 4;
            const float* Kp = g_K + ((size_t)bh*TOT + m0)*DH;
            const float* Vp = g_V + ((size_t)bh*TOT + m0)*DH;
#pragma unroll
            for (int rr = row; rr < 64; rr += 16) {
                float4 a = *(const float4*)(Kp + (size_t)rr*DH + d4*4);
                KT[(d4*4+0)*68 + rr] = a.x; KT[(d4*4+1)*68 + rr] = a.y;
                KT[(d4*4+2)*68 + rr] = a.z; KT[(d4*4+3)*68 + rr] = a.w;
                *(float4*)&VT[rr*68 + d4*4] = *(const float4*)(Vp + (size_t)rr*DH + d4*4);
            }
        }
        __syncthreads();

        // S = QU . K^T
        float S[4][4];
#pragma unroll
        for (int i = 0; i < 4; i++)
#pragma unroll
            for (int j = 0; j < 4; j++) S[i][j] = 0.f;
#pragma unroll 16
        for (int d = 0; d < 64; d++) {
            float4 a4 = *(float4*)&QT[d*68 + ty*4];
            float4 b4 = *(float4*)&KT[d*68 + tx*4];
            S[0][0] += a4.x*b4.x; S[0][1] += a4.x*b4.y; S[0][2] += a4.x*b4.z; S[0][3] += a4.x*b4.w;
            S[1][0] += a4.y*b4.x; S[1][1] += a4.y*b4.y; S[1][2] += a4.y*b4.z; S[1][3] += a4.y*b4.w;
            S[2][0] += a4.z*b4.x; S[2][1] += a4.z*b4.y; S[2][2] += a4.z*b4.z; S[2][3] += a4.z*b4.w;
            S[3][0] += a4.w*b4.x; S[3][1] += a4.w*b4.y; S[3][2] += a4.w*b4.z; S[3][3] += a4.w*b4.w;
        }

        // add shifted BD, scale, mask; online softmax update
#pragma unroll
        for (int i = 0; i < 4; i++) {
            float mx = -1e30f;
#pragma unroll
            for (int j = 0; j < 4; j++) {
                int m = m0 + tx*4 + j;
                S[i][j] = (m <= limit[i]) ? (S[i][j] + bdp[i][-m]) * 0.125f : -1e30f;
                mx = fmaxf(mx, S[i][j]);
            }
#pragma unroll
            for (int off = 8; off; off >>= 1)
                mx = fmaxf(mx, __shfl_xor_sync(0xffffffffu, mx, off));
            float Mn = fmaxf(M[i], mx);
            float alpha = __expf(M[i] - Mn);
            M[i] = Mn;
            float s = 0.f;
#pragma unroll
            for (int j = 0; j < 4; j++) {
                float p = __expf(S[i][j] - Mn);
                S[i][j] = p;
                s += p;
            }
#pragma unroll
            for (int off = 8; off; off >>= 1)
                s += __shfl_xor_sync(0xffffffffu, s, off);
            L[i] = L[i]*alpha + s;
#pragma unroll
            for (int j = 0; j < 4; j++) O[i][j] *= alpha;
            *(float4*)&PT[(ty*4+i)*68 + tx*4] = make_float4(S[i][0], S[i][1], S[i][2], S[i][3]);
        }
        __syncthreads();

        // O += P . V
#pragma unroll 8
        for (int mmm = 0; mmm < 64; mmm++) {
            float p0 = PT[(ty*4+0)*68 + mmm];
            float p1 = PT[(ty*4+1)*68 + mmm];
            float p2 = PT[(ty*4+2)*68 + mmm];
            float p3 = PT[(ty*4+3)*68 + mmm];
            float4 v4 = *(float4*)&VT[mmm*68 + tx*4];
            O[0][0] += p0*v4.x; O[0][1] += p0*v4.y; O[0][2] += p0*v4.z; O[0][3] += p0*v4.w;
            O[1][0] += p1*v4.x; O[1][1] += p1*v4.y; O[1][2] += p1*v4.z; O[1][3] += p1*v4.w;
            O[2][0] += p2*v4.x; O[2][1] += p2*v4.y; O[2][2] += p2*v4.z; O[2][3] += p2*v4.w;
            O[3][0] += p3*v4.x; O[3][1] += p3*v4.y; O[3][2] += p3*v4.z; O[3][3] += p3*v4.w;
        }
    }

#pragma unroll
    for (int i = 0; i < 4; i++) {
        int ng = n0 + ty*4 + i;
        float r = 1.f / L[i];
        float4 o = make_float4(O[i][0]*r, O[i][1]*r, O[i][2]*r, O[i][3]*r);
        *(float4*)&g_AO[((size_t)(b*SEQL + ng))*INNERD + h*DH + tx*4] = o;
    }
}

// =====================================================================
// Kernel 5: out = AO[2048 x 512] @ W_out[512 x 512] + b_out
// =====================================================================
__global__ __launch_bounds__(256) void out_kernel(
    const float* __restrict__ W, const float* __restrict__ bias,
    float* __restrict__ out)
{
    __shared__ float AsT[32][68];
    __shared__ float Bs [32][68];
    int t  = threadIdx.x;
    int tx = t & 15, ty = t >> 4;
    int r0 = blockIdx.y * 64;
    int c0 = blockIdx.x * 64;

    float acc[4][4];
#pragma unroll
    for (int i = 0; i < 4; i++)
#pragma unroll
        for (int j = 0; j < 4; j++) acc[i][j] = 0.f;

    for (int k0 = 0; k0 < INNERD; k0 += 32) {
        {
            int k4  = t & 7;
            int row = t >> 3;
#pragma unroll
            for (int rr = row; rr < 64; rr += 32) {
                int gr = r0 + rr;
                float4 v = *(const float4*)(g_AO + (size_t)gr*INNERD + k0 + k4*4);
                AsT[k4*4+0][rr] = v.x; AsT[k4*4+1][rr] = v.y;
                AsT[k4*4+2][rr] = v.z; AsT[k4*4+3][rr] = v.w;
            }
        }
        {
            int c4 = t & 15;
            int kr = t >> 4;
#pragma unroll
            for (int kk = kr; kk < 32; kk += 16) {
                float4 w = *(const float4*)(W + (size_t)(k0+kk)*DIMM + c0 + c4*4);
                *(float4*)&Bs[kk][c4*4] = w;
            }
        }
        __syncthreads();
#pragma unroll
        for (int kk = 0; kk < 32; kk++) {
            float4 a4 = *(float4*)&AsT[kk][ty*4];
            float4 b4 = *(float4*)&Bs [kk][tx*4];
            acc[0][0] += a4.x*b4.x; acc[0][1] += a4.x*b4.y; acc[0][2] += a4.x*b4.z; acc[0][3] += a4.x*b4.w;
            acc[1][0] += a4.y*b4.x; acc[1][1] += a4.y*b4.y; acc[1][2] += a4.y*b4.z; acc[1][3] += a4.y*b4.w;
            acc[2][0] += a4.z*b4.x; acc[2][1] += a4.z*b4.y; acc[2][2] += a4.z*b4.z; acc[2][3] += a4.z*b4.w;
            acc[3][0] += a4.w*b4.x; acc[3][1] += a4.w*b4.y; acc[3][2] += a4.w*b4.z; acc[3][3] += a4.w*b4.w;
        }
        __syncthreads();
    }

#pragma unroll
    for (int i = 0; i < 4; i++) {
        int gr = r0 + ty*4 + i;
#pragma unroll
        for (int j = 0; j < 4; j++) {
            int c = c0 + tx*4 + j;
            out[(size_t)gr*DIMM + c] = acc[i][j] + bias[c];
        }
    }
}

// =====================================================================
extern "C" void kernel_launch(void* const* d_in, const int* in_sizes, int n_in,
                              void* d_out, int out_size)
{
    const float* x      = (const float*)d_in[0];
    const float* memory = (const float*)d_in[1];
    const float* Wqkv   = (const float*)d_in[2];
    const float* Wrel   = (const float*)d_in[3];
    const float* Wout   = (const float*)d_in[4];
    const float* bout   = (const float*)d_in[5];
    const float* u_emb  = (const float*)d_in[6];
    const float* v_emb  = (const float*)d_in[7];
    float* out = (float*)d_out;

    (void)in_sizes; (void)n_in; (void)out_size;

    cudaFuncSetAttribute(attn_kernel, cudaFuncAttributeMaxDynamicSharedMemorySize,
                         ATTN_SMEM_FLOATS * (int)sizeof(float));

    // 1. QKV projection (8192 x 512) @ (512 x 1536)
    qkv_kernel<<<dim3(1536/128, 8192/128), 256>>>(x, memory, Wqkv, u_emb, v_emb);
    // 2. Krel = posenc @ W_rel
    krel_kernel<<<CTXL, 512>>>(Wrel);
    // 3. BD = QV . Krel^T (per b,h)
    bd_kernel<<<dim3(CTXL/64, SEQL/64, BB*NH), 256>>>();
    // 4. fused flash attention
    attn_kernel<<<dim3(SEQL/64, BB*NH), 256, ATTN_SMEM_FLOATS * (int)sizeof(float)>>>();
    // 5. output projection + bias
    out_kernel<<<dim3(DIMM/64, 2048/64), 256>>>(Wout, bout, out);
}